// round 1
// baseline (speedup 1.0000x reference)
#include <cuda_runtime.h>
#include <math.h>

#define NB 2
#define NS 2048
#define NHID 1024
#define NHEADS 16
#define HDIM 64
#define MM (NB * NS)   // 4096

// ---------------- scratch (static device globals; no allocation) ----------
__device__ float g_q[NB * NHEADS * NS * HDIM];   // [b,h,s,d]
__device__ float g_k[NB * NHEADS * NS * HDIM];
__device__ float g_v[NB * NHEADS * NS * HDIM];
__device__ float g_ao[NB * NS * NHID];           // [b,s,h*64+d]

// ---------------- packed f32x2 helpers ------------------------------------
__device__ __forceinline__ unsigned long long pk2(float a, float b) {
    unsigned long long r;
    asm("mov.b64 %0, {%1,%2};" : "=l"(r) : "f"(a), "f"(b));
    return r;
}
__device__ __forceinline__ void upk2(unsigned long long v, float& a, float& b) {
    asm("mov.b64 {%0,%1}, %2;" : "=f"(a), "=f"(b) : "l"(v));
}
__device__ __forceinline__ void ffma2(unsigned long long& c, unsigned long long a,
                                      unsigned long long b) {
    asm("fma.rn.f32x2 %0, %1, %2, %0;" : "+l"(c) : "l"(a), "l"(b));
}
__device__ __forceinline__ void fmul2(unsigned long long& c, unsigned long long a) {
    asm("mul.rn.f32x2 %0, %0, %1;" : "+l"(c) : "l"(a));
}

// ---------------------------------------------------------------------------
// GEMM: C[m,n] = sum_k A[m,k] * W[n,k] + bias[n]
// MODE 0/1/2: A = x, store to g_q/g_k/g_v in [b,h,s,d] layout
// MODE 3:     A = g_ao, store row-major to Cout
// Tiles: BM=BN=128, BK=16, 256 threads, 8x8 per thread (split 4+4 fragments).
// ---------------------------------------------------------------------------
template <int MODE>
__global__ __launch_bounds__(256) void gemm_xwt(const float* __restrict__ A,
                                                const float* __restrict__ W,
                                                const float* __restrict__ bias,
                                                float* __restrict__ Cout) {
    __shared__ float As[16][128];   // [k][m]
    __shared__ float Bs[16][128];   // [k][n]

    const int tid = threadIdx.x;
    const int m0 = blockIdx.y * 128;
    const int n0 = blockIdx.x * 128;
    const int ry = tid >> 4;    // 0..15
    const int tx = tid & 15;    // 0..15

    const float* Ap = (MODE == 3) ? g_ao : A;

    // staging: each thread loads 2 float4 of A and 2 float4 of W per k-tile
    const int lrow = tid >> 1;            // 0..127
    const int cgb  = (tid & 1) * 2;       // 0 or 2 (float4-group base)

    const float* ga = Ap + (size_t)(m0 + lrow) * NHID + cgb * 4;
    const float* gw = W  + (size_t)(n0 + lrow) * NHID + cgb * 4;

    unsigned long long acc[4][8];
#pragma unroll
    for (int i = 0; i < 4; i++)
#pragma unroll
        for (int j = 0; j < 8; j++) acc[i][j] = 0ull;

    float4 pa0 = *(const float4*)(ga);
    float4 pa1 = *(const float4*)(ga + 4);
    float4 pw0 = *(const float4*)(gw);
    float4 pw1 = *(const float4*)(gw + 4);

    const int NKT = NHID / 16;   // 64
    for (int kt = 0; kt < NKT; kt++) {
        // transpose-store staged frags into k-major smem
        As[4 * cgb + 0][lrow] = pa0.x;
        As[4 * cgb + 1][lrow] = pa0.y;
        As[4 * cgb + 2][lrow] = pa0.z;
        As[4 * cgb + 3][lrow] = pa0.w;
        As[4 * cgb + 4][lrow] = pa1.x;
        As[4 * cgb + 5][lrow] = pa1.y;
        As[4 * cgb + 6][lrow] = pa1.z;
        As[4 * cgb + 7][lrow] = pa1.w;
        Bs[4 * cgb + 0][lrow] = pw0.x;
        Bs[4 * cgb + 1][lrow] = pw0.y;
        Bs[4 * cgb + 2][lrow] = pw0.z;
        Bs[4 * cgb + 3][lrow] = pw0.w;
        Bs[4 * cgb + 4][lrow] = pw1.x;
        Bs[4 * cgb + 5][lrow] = pw1.y;
        Bs[4 * cgb + 6][lrow] = pw1.z;
        Bs[4 * cgb + 7][lrow] = pw1.w;
        __syncthreads();

        if (kt + 1 < NKT) {   // register prefetch of next k-tile
            const float* ga2 = ga + (kt + 1) * 16;
            const float* gw2 = gw + (kt + 1) * 16;
            pa0 = *(const float4*)(ga2);
            pa1 = *(const float4*)(ga2 + 4);
            pw0 = *(const float4*)(gw2);
            pw1 = *(const float4*)(gw2 + 4);
        }

#pragma unroll
        for (int kk = 0; kk < 16; kk++) {
            ulonglong2 a01 = *(const ulonglong2*)&As[kk][4 * ry];
            ulonglong2 a23 = *(const ulonglong2*)&As[kk][64 + 4 * ry];
            float4 b0 = *(const float4*)&Bs[kk][4 * tx];
            float4 b1 = *(const float4*)&Bs[kk][64 + 4 * tx];
            unsigned long long av[4] = {a01.x, a01.y, a23.x, a23.y};
            unsigned long long bd[8] = {pk2(b0.x, b0.x), pk2(b0.y, b0.y),
                                        pk2(b0.z, b0.z), pk2(b0.w, b0.w),
                                        pk2(b1.x, b1.x), pk2(b1.y, b1.y),
                                        pk2(b1.z, b1.z), pk2(b1.w, b1.w)};
#pragma unroll
            for (int i = 0; i < 4; i++)
#pragma unroll
                for (int j = 0; j < 8; j++) ffma2(acc[i][j], av[i], bd[j]);
        }
        __syncthreads();
    }

    // epilogue
#pragma unroll
    for (int i = 0; i < 4; i++) {
        const int rbase = (i < 2) ? (4 * ry + 2 * i) : (64 + 4 * ry + 2 * (i - 2));
#pragma unroll
        for (int j = 0; j < 8; j++) {
            const int col = (j < 4) ? (4 * tx + j) : (64 + 4 * tx + (j - 4));
            float v0, v1;
            upk2(acc[i][j], v0, v1);
            const float bv = bias[n0 + col];
            v0 += bv;
            v1 += bv;
            const int m = m0 + rbase;   // always even
            const int n = n0 + col;
            if (MODE == 3) {
                Cout[(size_t)m * NHID + n] = v0;
                Cout[(size_t)(m + 1) * NHID + n] = v1;
            } else {
                float* dst = (MODE == 0) ? g_q : (MODE == 1) ? g_k : g_v;
                const int b = m >> 11;          // m / NS
                const int s = m & (NS - 1);
                const int h = n >> 6;           // n / HDIM
                const int d = n & (HDIM - 1);
                const size_t base = (((size_t)(b * NHEADS + h) * NS + s) * HDIM + d);
                dst[base] = v0;
                dst[base + HDIM] = v1;          // row m+1 -> s+1 (same b,h: s even)
            }
        }
    }
}

// ---------------------------------------------------------------------------
// RoPE in-place on g_q and g_k. One thread per (tensor, b, h, s, d<32) pair.
// Double-precision angle -> exact cos/sin (reference fp32 deviates <=1.2e-4).
// ---------------------------------------------------------------------------
__global__ void rope_kernel() {
    int t = blockIdx.x * blockDim.x + threadIdx.x;
    const int half = NB * NHEADS * NS * 32;   // 2,097,152
    float* base = g_q;
    if (t >= half) {
        base = g_k;
        t -= half;
    }
    const int d = t & 31;
    const int s = (t >> 5) & (NS - 1);
    const int bh = t >> 16;   // t / (32*NS)

    // inv_freq = 10000^(-d/32) = 2^(-d * log2(10000)/32)
    const double inv = exp2(-(double)d * 0.41524101186092029);
    const double ang = (double)s * inv;
    double sd, cd;
    sincos(ang, &sd, &cd);
    const float c = (float)cd;
    const float sn = (float)sd;

    float* p = base + ((size_t)bh * NS + s) * HDIM + d;
    const float x1 = p[0];
    const float x2 = p[32];
    p[0] = x1 * c - x2 * sn;
    p[32] = x2 * c + x1 * sn;
}

// ---------------------------------------------------------------------------
// Flash attention (causal). One CTA per (b, h, 64-row q tile).
// smem: Qdup[64d][128] (q duplicated, pre-scaled), Kt[64d][64k],
//       Vs[64k][64d], Pdup[64k][128] (p duplicated).
// 256 threads: ty=tid/16 -> 4 q rows (S-phase) / 4 q rows (O-phase),
//              tx=tid%16 -> 4 k cols (S) / 4 d cols (O).
// All inner-product smem reads are conflict-free LDS.128; FMAs are f32x2.
// ---------------------------------------------------------------------------
__global__ __launch_bounds__(256) void attn_kernel() {
    extern __shared__ float sm[];
    float* Qd = sm;                  // 64*128
    float* Kt = sm + 64 * 128;       // 64*64
    float* Vs = Kt + 64 * 64;        // 64*64
    float* Pd = Vs + 64 * 64;        // 64*128

    const int qt = (int)(gridDim.x - 1) - (int)blockIdx.x;  // big tiles first
    const int h = blockIdx.y;
    const int b = blockIdx.z;
    const int tid = threadIdx.x;
    const int ty = tid >> 4;
    const int tx = tid & 15;

    const float* Qg = g_q + ((size_t)(b * NHEADS + h) * NS + (size_t)qt * 64) * HDIM;
    const float* Kg = g_k + (size_t)(b * NHEADS + h) * NS * HDIM;
    const float* Vg = g_v + (size_t)(b * NHEADS + h) * NS * HDIM;

    // load Q tile: scaled by 1/sqrt(64), transposed + duplicated: Qd[d][2q],[2q+1]
#pragma unroll
    for (int p = 0; p < 4; p++) {
        const int fid = tid + 256 * p;
        const int row = fid >> 4;
        const int cg = fid & 15;
        float4 v = *(const float4*)(Qg + (size_t)row * HDIM + cg * 4);
        v.x *= 0.125f; v.y *= 0.125f; v.z *= 0.125f; v.w *= 0.125f;
        Qd[(4 * cg + 0) * 128 + 2 * row] = v.x;
        Qd[(4 * cg + 0) * 128 + 2 * row + 1] = v.x;
        Qd[(4 * cg + 1) * 128 + 2 * row] = v.y;
        Qd[(4 * cg + 1) * 128 + 2 * row + 1] = v.y;
        Qd[(4 * cg + 2) * 128 + 2 * row] = v.z;
        Qd[(4 * cg + 2) * 128 + 2 * row + 1] = v.z;
        Qd[(4 * cg + 3) * 128 + 2 * row] = v.w;
        Qd[(4 * cg + 3) * 128 + 2 * row + 1] = v.w;
    }

    const float NEG_INF = __int_as_float(0xff800000);
    float mi[4], li[4];
    unsigned long long o2[4][2];
#pragma unroll
    for (int i = 0; i < 4; i++) {
        mi[i] = NEG_INF;
        li[i] = 0.0f;
        o2[i][0] = 0ull;
        o2[i][1] = 0ull;
    }

    for (int kt = 0; kt <= qt; kt++) {
        __syncthreads();   // previous O-phase done with Kt/Vs/Pd
        // load K (transposed) and V tiles
#pragma unroll
        for (int p = 0; p < 4; p++) {
            const int fid = tid + 256 * p;
            const int row = fid >> 4;
            const int cg = fid & 15;
            const size_t goff = ((size_t)kt * 64 + row) * HDIM + cg * 4;
            float4 kv = *(const float4*)(Kg + goff);
            Kt[(4 * cg + 0) * 64 + row] = kv.x;
            Kt[(4 * cg + 1) * 64 + row] = kv.y;
            Kt[(4 * cg + 2) * 64 + row] = kv.z;
            Kt[(4 * cg + 3) * 64 + row] = kv.w;
            float4 vv = *(const float4*)(Vg + goff);
            *(float4*)&Vs[row * 64 + cg * 4] = vv;
        }
        __syncthreads();

        // ---- S = (Q/8) @ K^T  (64x64 tile) ----
        unsigned long long s2[4][2];
#pragma unroll
        for (int i = 0; i < 4; i++) { s2[i][0] = 0ull; s2[i][1] = 0ull; }

#pragma unroll 8
        for (int d = 0; d < 64; d++) {
            ulonglong2 a01 = *(const ulonglong2*)&Qd[d * 128 + 8 * ty];
            ulonglong2 a23 = *(const ulonglong2*)&Qd[d * 128 + 8 * ty + 4];
            ulonglong2 bb = *(const ulonglong2*)&Kt[d * 64 + 4 * tx];
            unsigned long long av[4] = {a01.x, a01.y, a23.x, a23.y};
#pragma unroll
            for (int i = 0; i < 4; i++) {
                ffma2(s2[i][0], av[i], bb.x);
                ffma2(s2[i][1], av[i], bb.y);
            }
        }

        float sv[4][4];
#pragma unroll
        for (int i = 0; i < 4; i++) {
            upk2(s2[i][0], sv[i][0], sv[i][1]);
            upk2(s2[i][1], sv[i][2], sv[i][3]);
        }

        if (kt == qt) {   // causal mask on the diagonal tile (local indices)
#pragma unroll
            for (int i = 0; i < 4; i++) {
                const int qg = 4 * ty + i;
#pragma unroll
                for (int c = 0; c < 4; c++)
                    if (4 * tx + c > qg) sv[i][c] = -1e30f;
            }
        }

        // ---- online softmax + write duplicated P ----
#pragma unroll
        for (int i = 0; i < 4; i++) {
            float mx = fmaxf(fmaxf(sv[i][0], sv[i][1]), fmaxf(sv[i][2], sv[i][3]));
#pragma unroll
            for (int o = 1; o < 16; o <<= 1)
                mx = fmaxf(mx, __shfl_xor_sync(0xffffffffu, mx, o));
            const float mnew = fmaxf(mi[i], mx);
            const float corr = __expf(mi[i] - mnew);
            float ps0 = __expf(sv[i][0] - mnew);
            float ps1 = __expf(sv[i][1] - mnew);
            float ps2 = __expf(sv[i][2] - mnew);
            float ps3 = __expf(sv[i][3] - mnew);
            float rs = (ps0 + ps1) + (ps2 + ps3);
#pragma unroll
            for (int o = 1; o < 16; o <<= 1)
                rs += __shfl_xor_sync(0xffffffffu, rs, o);
            li[i] = li[i] * corr + rs;
            mi[i] = mnew;
            const unsigned long long c2 = pk2(corr, corr);
            fmul2(o2[i][0], c2);
            fmul2(o2[i][1], c2);
            const int q2 = 8 * ty + 2 * i;
            Pd[(4 * tx + 0) * 128 + q2] = ps0;
            Pd[(4 * tx + 0) * 128 + q2 + 1] = ps0;
            Pd[(4 * tx + 1) * 128 + q2] = ps1;
            Pd[(4 * tx + 1) * 128 + q2 + 1] = ps1;
            Pd[(4 * tx + 2) * 128 + q2] = ps2;
            Pd[(4 * tx + 2) * 128 + q2 + 1] = ps2;
            Pd[(4 * tx + 3) * 128 + q2] = ps3;
            Pd[(4 * tx + 3) * 128 + q2 + 1] = ps3;
        }
        __syncthreads();

        // ---- O += P @ V ----
#pragma unroll 8
        for (int k = 0; k < 64; k++) {
            ulonglong2 p01 = *(const ulonglong2*)&Pd[k * 128 + 8 * ty];
            ulonglong2 p23 = *(const ulonglong2*)&Pd[k * 128 + 8 * ty + 4];
            ulonglong2 vv = *(const ulonglong2*)&Vs[k * 64 + 4 * tx];
            unsigned long long av[4] = {p01.x, p01.y, p23.x, p23.y};
#pragma unroll
            for (int i = 0; i < 4; i++) {
                ffma2(o2[i][0], av[i], vv.x);
                ffma2(o2[i][1], av[i], vv.y);
            }
        }
    }

    // ---- normalize and store to g_ao [b, s, h*64+d] ----
    float* Og = g_ao + ((size_t)b * NS + (size_t)qt * 64) * NHID + h * HDIM;
#pragma unroll
    for (int i = 0; i < 4; i++) {
        const float inv = 1.0f / li[i];
        float v0, v1, v2, v3;
        upk2(o2[i][0], v0, v1);
        upk2(o2[i][1], v2, v3);
        const int row = 4 * ty + i;
        float* op = Og + (size_t)row * NHID + 4 * tx;
        op[0] = v0 * inv;
        op[1] = v1 * inv;
        op[2] = v2 * inv;
        op[3] = v3 * inv;
    }
}

// ---------------------------------------------------------------------------
extern "C" void kernel_launch(void* const* d_in, const int* in_sizes, int n_in,
                              void* d_out, int out_size) {
    const float* x  = (const float*)d_in[0];
    const float* Wq = (const float*)d_in[1];
    const float* bq = (const float*)d_in[2];
    const float* Wk = (const float*)d_in[3];
    const float* bk = (const float*)d_in[4];
    const float* Wv = (const float*)d_in[5];
    const float* bv = (const float*)d_in[6];
    const float* Wo = (const float*)d_in[7];
    const float* bo = (const float*)d_in[8];
    // d_in[9] = mask (causal tril) -- implemented analytically in attn_kernel
    float* out = (float*)d_out;

    cudaFuncSetAttribute(attn_kernel, cudaFuncAttributeMaxDynamicSharedMemorySize,
                         96 * 1024);

    const dim3 gg(NHID / 128, MM / 128);   // (8, 32)
    gemm_xwt<0><<<gg, 256>>>(x, Wq, bq, nullptr);
    gemm_xwt<1><<<gg, 256>>>(x, Wk, bk, nullptr);
    gemm_xwt<2><<<gg, 256>>>(x, Wv, bv, nullptr);

    const int rope_threads = 2 * NB * NHEADS * NS * 32;
    rope_kernel<<<rope_threads / 256, 256>>>();

    attn_kernel<<<dim3(NS / 64, NHEADS, NB), 256, 96 * 1024>>>();

    gemm_xwt<3><<<gg, 256>>>(nullptr, Wo, bo, out);
}